// round 16
// baseline (speedup 1.0000x reference)
#include <cuda_runtime.h>
#include <cuda_fp16.h>
#include <cstdint>
#include <math.h>

#define D_MODEL 1024
#define NH      16
#define DH      64
#define B_      2
#define S_      2048
#define M_TOK   (B_ * S_)

// ---------------- scratch (allocation-free) ----------------
__device__ __half g_X [M_TOK * D_MODEL];
__device__ __half g_Wq[D_MODEL * D_MODEL];
__device__ __half g_Wk[D_MODEL * D_MODEL];
__device__ __half g_Wv[D_MODEL * D_MODEL];
__device__ __half g_Wo[D_MODEL * D_MODEL];
__device__ __half g_Q [M_TOK * D_MODEL];
__device__ __half g_K [M_TOK * D_MODEL];
__device__ __half g_V [M_TOK * D_MODEL];
__device__ __half g_A [M_TOK * D_MODEL];

// ---------------- helpers ----------------
__device__ __forceinline__ uint32_t pack_h2(float a, float b) {
    __half2 h = __floats2half2_rn(a, b);
    return *(uint32_t*)&h;
}
__device__ __forceinline__ void mma_f16(float* c, const uint32_t* a, const uint32_t* b) {
    asm volatile(
        "mma.sync.aligned.m16n8k16.row.col.f32.f16.f16.f32 "
        "{%0,%1,%2,%3}, {%4,%5,%6,%7}, {%8,%9}, {%0,%1,%2,%3};"
        : "+f"(c[0]), "+f"(c[1]), "+f"(c[2]), "+f"(c[3])
        : "r"(a[0]), "r"(a[1]), "r"(a[2]), "r"(a[3]), "r"(b[0]), "r"(b[1]));
}
__device__ __forceinline__ void ldsm_x4(uint32_t* r, uint32_t addr) {
    asm volatile("ldmatrix.sync.aligned.m8n8.x4.shared.b16 {%0,%1,%2,%3}, [%4];"
        : "=r"(r[0]), "=r"(r[1]), "=r"(r[2]), "=r"(r[3]) : "r"(addr));
}
__device__ __forceinline__ void ldsm_x4_t(uint32_t* r, uint32_t addr) {
    asm volatile("ldmatrix.sync.aligned.m8n8.x4.trans.shared.b16 {%0,%1,%2,%3}, [%4];"
        : "=r"(r[0]), "=r"(r[1]), "=r"(r[2]), "=r"(r[3]) : "r"(addr));
}
__device__ __forceinline__ uint32_t smem_u32(const void* p) {
    uint32_t a;
    asm("{ .reg .u64 t; cvta.to.shared.u64 t, %1; cvt.u32.u64 %0, t; }" : "=r"(a) : "l"(p));
    return a;
}
__device__ __forceinline__ void cp_async16(uint32_t dst, const void* src) {
    asm volatile("cp.async.cg.shared.global [%0], [%1], 16;" :: "r"(dst), "l"(src));
}
#define CP_COMMIT() asm volatile("cp.async.commit_group;" ::: "memory")
#define CP_WAIT1()  asm volatile("cp.async.wait_group 1;"  ::: "memory")

// ============================================================================
// Fused fp32 -> fp16 convert for all 5 tensors (unchanged — at L2 floor)
// ============================================================================
#define X4SZ (M_TOK * D_MODEL / 4)
#define W4SZ (D_MODEL * D_MODEL / 4)
#define TOT4 (X4SZ + 4 * W4SZ)

__global__ __launch_bounds__(256) void cvt_all_kernel(
    const float* __restrict__ x,
    const float* __restrict__ wq, const float* __restrict__ wk,
    const float* __restrict__ wv, const float* __restrict__ wo,
    __half* __restrict__ xd,
    __half* __restrict__ wqd, __half* __restrict__ wkd,
    __half* __restrict__ wvd, __half* __restrict__ wod)
{
    for (int i = blockIdx.x * blockDim.x + threadIdx.x; i < TOT4;
         i += gridDim.x * blockDim.x) {
        const float* src; __half* dst; int j;
        if (i < X4SZ) { src = x; dst = xd; j = i; }
        else {
            const int r = i - X4SZ;
            const int s = r >> 18;
            j = r & (W4SZ - 1);
            src = (s == 0) ? wq : (s == 1) ? wk : (s == 2) ? wv : wo;
            dst = (s == 0) ? wqd : (s == 1) ? wkd : (s == 2) ? wvd : wod;
        }
        float4 v = ((const float4*)src)[j];
        ((uint2*)dst)[j] = make_uint2(pack_h2(v.x, v.y), pack_h2(v.z, v.w));
    }
}

// ============================================================================
// All-fp16 NT-GEMM v6: CTA 128x128, 4 warps (2m x 2n) 64x64 warp tiles,
// k-chunk 64, 2-stage cp.async double buffer, __launch_bounds__(128, 3):
// 3 CTAs/SM (12 warps) — third CTA fills barrier/wait convoy gaps.
// smem: 2 stages x 9216 words = 73728 B.
// ============================================================================
#define G2STR  36
#define G2SST  (256 * G2STR)             // 9216 words per stage
#define GEMM_SMEM (2 * G2SST * 4)        // 73728 B
#define KITER  (D_MODEL / 64)            // 16

template <bool QKV>
__global__ __launch_bounds__(128, 3) void gemm_f16cp_kernel(
    const __half* __restrict__ A,
    const __half* __restrict__ Wa, const __half* __restrict__ Wb,
    const __half* __restrict__ Wc,
    void* __restrict__ Ca, void* __restrict__ Cb, void* __restrict__ Cc)
{
    extern __shared__ uint32_t sm[];
    const uint32_t sbase = smem_u32(sm);

    const __half* W;
    void* Cv;
    float psc = 1.0f;
    if (QKV) {
        const int z = blockIdx.z;
        W   = (z == 0) ? Wa : (z == 1) ? Wb : Wc;
        Cv  = (z == 0) ? Ca : (z == 1) ? Cb : Cc;
        psc = (z == 0) ? 0.125f : 1.0f;
    } else {
        W = Wa; Cv = Ca;
    }

    const int tid  = threadIdx.x;
    const int wid  = tid >> 5;
    const int lane = tid & 31;
    const int m0   = blockIdx.y * 128;
    const int n0   = blockIdx.x * 128;
    const int wm   = (wid & 1) * 64;
    const int wn   = (wid >> 1) * 64;

    const int srow = tid >> 3;
    const int sch  = tid & 7;
    auto issue = [&](int i, int p) {
        const int k0 = i * 64;
#pragma unroll
        for (int j = 0; j < 16; j++) {
            const int row = srow + (j & 7) * 16;
            const __half* src = (j < 8)
                ? A + (size_t)(m0 + row) * D_MODEL + k0 + sch * 8
                : W + (size_t)(n0 + row) * D_MODEL + k0 + sch * 8;
            const int lrow = (j < 8) ? row : row + 128;
            cp_async16(sbase + 4 * (p * G2SST + lrow * G2STR + sch * 4), src);
        }
    };

    const int a_off = (lane & 15) * G2STR + (lane >> 4) * 4;
    const int b_off = ((lane & 7) + (lane >> 4) * 8) * G2STR + ((lane >> 3) & 1) * 4;

    float acc[4][8][4];
#pragma unroll
    for (int mt = 0; mt < 4; mt++)
#pragma unroll
        for (int nt = 0; nt < 8; nt++)
#pragma unroll
            for (int e = 0; e < 4; e++) acc[mt][nt][e] = 0.f;

    issue(0, 0); CP_COMMIT();
    issue(1, 1); CP_COMMIT();

    for (int i = 0; i < KITER; i++) {
        CP_WAIT1();              // stage i complete (stage i+1 may be pending)
        __syncthreads();

        const int p = i & 1;
        const uint32_t sA = sbase + 4 * (p * G2SST);
        const uint32_t sB = sbase + 4 * (p * G2SST + 128 * G2STR);

#pragma unroll
        for (int ks = 0; ks < 4; ks++) {
            uint32_t a[4][4], b[4][4];
#pragma unroll
            for (int ma = 0; ma < 4; ma++)
                ldsm_x4(a[ma], sA + 4 * ((wm + ma * 16) * G2STR + ks * 8 + a_off));
#pragma unroll
            for (int nb = 0; nb < 4; nb++)
                ldsm_x4(b[nb], sB + 4 * ((wn + nb * 16) * G2STR + ks * 8 + b_off));
#pragma unroll
            for (int ma = 0; ma < 4; ma++)
#pragma unroll
                for (int nb = 0; nb < 4; nb++) {
                    mma_f16(acc[ma][2 * nb],     a[ma], &b[nb][0]);
                    mma_f16(acc[ma][2 * nb + 1], a[ma], &b[nb][2]);
                }
        }

        __syncthreads();         // all warps done reading buffer p
        if (i + 2 < KITER) issue(i + 2, p);
        CP_COMMIT();
    }

    const int row  = lane >> 2;
    const int col2 = (lane & 3) * 2;
#pragma unroll
    for (int mt = 0; mt < 4; mt++) {
        const int m = m0 + wm + mt * 16 + row;
#pragma unroll
        for (int nt = 0; nt < 8; nt++) {
            const int n = n0 + wn + nt * 8 + col2;
            if (QKV) {
                uint32_t h01 = pack_h2(acc[mt][nt][0] * psc, acc[mt][nt][1] * psc);
                uint32_t h23 = pack_h2(acc[mt][nt][2] * psc, acc[mt][nt][3] * psc);
                const int b = m >> 11, s = m & 2047, h = n >> 6, d = n & 63;
                __half* dst = (__half*)Cv + (((size_t)(b * NH + h) * S_) + s) * DH + d;
                *(uint32_t*)dst = h01;
                *(uint32_t*)(dst + (size_t)8 * DH) = h23;
            } else {
                float* dst = (float*)Cv + (size_t)m * D_MODEL + n;
                *(float2*)dst = make_float2(acc[mt][nt][0], acc[mt][nt][1]);
                *(float2*)(dst + 8 * D_MODEL) = make_float2(acc[mt][nt][2], acc[mt][nt][3]);
            }
        }
    }
}

// ============================================================================
// fp16 flash attention (R14 version — known good): 8 warps x 16-row tiles,
// Bc=64, 3-stage cp.async, globally-descending CTA work order.
// ============================================================================
#define KVS    36
#define VOFFW  (64 * KVS)
#define KVW    (2 * 64 * KVS)
#define PSOFF  (3 * KVW)
#define PSTR   36
#define ATT_SMEM ((PSOFF + 8 * 16 * PSTR) * 4)   // 73728 B

__global__ __launch_bounds__(256, 2) void attn_f16_kernel(
    const __half* __restrict__ Q,
    const __half* __restrict__ K,
    const __half* __restrict__ V,
    __half* __restrict__ O)
{
    extern __shared__ uint32_t sm[];
    const uint32_t sbase = smem_u32(sm);

    const int tid  = threadIdx.x;
    const int wid  = tid >> 5;
    const int lane = tid & 31;
    const int gid  = lane >> 2;
    const int tig  = lane & 3;
    const int bh   = blockIdx.x;
    const int qblk = gridDim.y - 1 - blockIdx.y;
    const int qr0  = qblk * 128 + wid * 16;
    const int ntiles = qblk * 2 + 2;

    const int crow = tid >> 2;
    const int cch  = (tid & 3) * 2;
    const __half* Kg = K + (size_t)bh * S_ * DH;
    const __half* Vg = V + (size_t)bh * S_ * DH;

    auto issue_tile = [&](int t, int p) {
        const size_t row = (size_t)t * 64 + crow;
#pragma unroll
        for (int j = 0; j < 2; j++) {
            const int ch = cch + j;
            cp_async16(sbase + 4 * (p * KVW + crow * KVS + ch * 4),
                       Kg + row * DH + ch * 8);
            cp_async16(sbase + 4 * (p * KVW + VOFFW + crow * KVS + ch * 4),
                       Vg + row * DH + ch * 8);
        }
    };

    const int kb_off = ((lane & 7) + (lane >> 4) * 8) * KVS + ((lane >> 3) & 1) * 4;
    const int v_off  = (lane & 15) * KVS + (lane >> 4) * 4;
    const int p_off  = ((lane & 7) + ((lane >> 3) & 1) * 8) * PSTR + (lane >> 4) * 4;

    const uint32_t* Qw = (const uint32_t*)(Q + ((size_t)bh * S_ + qr0) * DH);
    uint32_t qa[4][4];
#pragma unroll
    for (int ks = 0; ks < 4; ks++) {
        qa[ks][0] = Qw[(size_t)gid * 32 + ks * 8 + tig];
        qa[ks][1] = Qw[(size_t)(gid + 8) * 32 + ks * 8 + tig];
        qa[ks][2] = Qw[(size_t)gid * 32 + ks * 8 + tig + 4];
        qa[ks][3] = Qw[(size_t)(gid + 8) * 32 + ks * 8 + tig + 4];
    }

    float o[8][4];
#pragma unroll
    for (int dt = 0; dt < 8; dt++)
#pragma unroll
        for (int e = 0; e < 4; e++) o[dt][e] = 0.f;
    float mr0 = -1e30f, mr1 = -1e30f;
    float lr0 = 0.f, lr1 = 0.f;

    issue_tile(0, 0); CP_COMMIT();
    issue_tile(1, 1); CP_COMMIT();

    uint32_t* Pw = sm + PSOFF + wid * 16 * PSTR;
    const uint32_t pwbase = sbase + 4 * (PSOFF + wid * 16 * PSTR);

    for (int t = 0; t < ntiles; t++) {
        CP_WAIT1();
        __syncthreads();

        if (t + 2 < ntiles) issue_tile(t + 2, (t + 2) % 3);
        CP_COMMIT();

        const int krow0 = t * 64;
        const int p = t % 3;

        if (krow0 <= qr0 + 15) {
            const uint32_t kbase = sbase + 4 * (p * KVW);
            const uint32_t vbase = sbase + 4 * (p * KVW + VOFFW);

            float sc[8][4];
#pragma unroll
            for (int nt = 0; nt < 8; nt++)
#pragma unroll
                for (int e = 0; e < 4; e++) sc[nt][e] = 0.f;
#pragma unroll
            for (int ks = 0; ks < 4; ks++) {
                uint32_t bk[4][4];
#pragma unroll
                for (int g = 0; g < 4; g++)
                    ldsm_x4(bk[g], kbase + 4 * (g * 16 * KVS + ks * 8 + kb_off));
#pragma unroll
                for (int nt = 0; nt < 8; nt++)
                    mma_f16(sc[nt], qa[ks], &bk[nt >> 1][(nt & 1) * 2]);
            }

            const int row0 = qr0 + gid;
            const int row1 = qr0 + 8 + gid;
            if (krow0 + 63 > qr0) {
#pragma unroll
                for (int nt = 0; nt < 8; nt++) {
                    const int kc = krow0 + nt * 8 + 2 * tig;
                    if (kc > row0)     sc[nt][0] = -1e30f;
                    if (kc + 1 > row0) sc[nt][1] = -1e30f;
                    if (kc > row1)     sc[nt][2] = -1e30f;
                    if (kc + 1 > row1) sc[nt][3] = -1e30f;
                }
            }

            float tmax0 = -1e30f, tmax1 = -1e30f;
#pragma unroll
            for (int nt = 0; nt < 8; nt++) {
                tmax0 = fmaxf(tmax0, fmaxf(sc[nt][0], sc[nt][1]));
                tmax1 = fmaxf(tmax1, fmaxf(sc[nt][2], sc[nt][3]));
            }
            tmax0 = fmaxf(tmax0, __shfl_xor_sync(0xffffffffu, tmax0, 1));
            tmax0 = fmaxf(tmax0, __shfl_xor_sync(0xffffffffu, tmax0, 2));
            tmax1 = fmaxf(tmax1, __shfl_xor_sync(0xffffffffu, tmax1, 1));
            tmax1 = fmaxf(tmax1, __shfl_xor_sync(0xffffffffu, tmax1, 2));

            const float mn0 = fmaxf(mr0, tmax0);
            const float mn1 = fmaxf(mr1, tmax1);
            const float cr0 = __expf(mr0 - mn0);
            const float cr1 = __expf(mr1 - mn1);

            float sum0 = 0.f, sum1 = 0.f;
#pragma unroll
            for (int nt = 0; nt < 8; nt++) {
                float p0 = __expf(sc[nt][0] - mn0);
                float p1 = __expf(sc[nt][1] - mn0);
                float p2 = __expf(sc[nt][2] - mn1);
                float p3 = __expf(sc[nt][3] - mn1);
                sum0 += p0 + p1;
                sum1 += p2 + p3;
                Pw[gid * PSTR + nt * 4 + tig]       = pack_h2(p0, p1);
                Pw[(gid + 8) * PSTR + nt * 4 + tig] = pack_h2(p2, p3);
            }
            sum0 += __shfl_xor_sync(0xffffffffu, sum0, 1);
            sum0 += __shfl_xor_sync(0xffffffffu, sum0, 2);
            sum1 += __shfl_xor_sync(0xffffffffu, sum1, 1);
            sum1 += __shfl_xor_sync(0xffffffffu, sum1, 2);

            lr0 = lr0 * cr0 + sum0;
            lr1 = lr1 * cr1 + sum1;
#pragma unroll
            for (int dt = 0; dt < 8; dt++) {
                o[dt][0] *= cr0; o[dt][1] *= cr0;
                o[dt][2] *= cr1; o[dt][3] *= cr1;
            }
            mr0 = mn0; mr1 = mn1;
            __syncwarp();

#pragma unroll
            for (int kb = 0; kb < 4; kb++) {
                uint32_t pa[4];
                ldsm_x4(pa, pwbase + 4 * (kb * 8 + p_off));
#pragma unroll
                for (int dp = 0; dp < 4; dp++) {
                    uint32_t bv[4];
                    ldsm_x4_t(bv, vbase + 4 * (kb * 16 * KVS + dp * 8 + v_off));
                    mma_f16(o[2 * dp],     pa, &bv[0]);
                    mma_f16(o[2 * dp + 1], pa, &bv[2]);
                }
            }
            __syncwarp();
        }
    }

    const int b  = bh / NH;
    const int h  = bh % NH;
    const float inv0 = 1.f / lr0;
    const float inv1 = 1.f / lr1;
    const int row0 = qr0 + gid;
    const int row1 = qr0 + 8 + gid;
    __half* op0 = O + ((size_t)(b * S_ + row0)) * D_MODEL + h * DH;
    __half* op1 = O + ((size_t)(b * S_ + row1)) * D_MODEL + h * DH;
#pragma unroll
    for (int dt = 0; dt < 8; dt++) {
        const int d = dt * 8 + 2 * tig;
        *(uint32_t*)(op0 + d) = pack_h2(o[dt][0] * inv0, o[dt][1] * inv0);
        *(uint32_t*)(op1 + d) = pack_h2(o[dt][2] * inv1, o[dt][3] * inv1);
    }
}

// ============================================================================
// launch
// ============================================================================
extern "C" void kernel_launch(void* const* d_in, const int* in_sizes, int n_in,
                              void* d_out, int out_size)
{
    const float* x  = (const float*)d_in[0];
    const float* Wq = (const float*)d_in[1];
    const float* Wk = (const float*)d_in[2];
    const float* Wv = (const float*)d_in[3];
    const float* Wo = (const float*)d_in[4];
    float* out = (float*)d_out;

    __half *Xp, *Wqp, *Wkp, *Wvp, *Wop, *Qp, *Kp, *Vp, *Ap;
    cudaGetSymbolAddress((void**)&Xp,  g_X);
    cudaGetSymbolAddress((void**)&Wqp, g_Wq);
    cudaGetSymbolAddress((void**)&Wkp, g_Wk);
    cudaGetSymbolAddress((void**)&Wvp, g_Wv);
    cudaGetSymbolAddress((void**)&Wop, g_Wo);
    cudaGetSymbolAddress((void**)&Qp,  g_Q);
    cudaGetSymbolAddress((void**)&Kp,  g_K);
    cudaGetSymbolAddress((void**)&Vp,  g_V);
    cudaGetSymbolAddress((void**)&Ap,  g_A);

    cudaFuncSetAttribute(gemm_f16cp_kernel<true>,
                         cudaFuncAttributeMaxDynamicSharedMemorySize, GEMM_SMEM);
    cudaFuncSetAttribute(gemm_f16cp_kernel<false>,
                         cudaFuncAttributeMaxDynamicSharedMemorySize, GEMM_SMEM);
    cudaFuncSetAttribute(attn_f16_kernel,
                         cudaFuncAttributeMaxDynamicSharedMemorySize, ATT_SMEM);

    cvt_all_kernel<<<2048, 256>>>(x, Wq, Wk, Wv, Wo, Xp, Wqp, Wkp, Wvp, Wop);

    dim3 qkvgrid(D_MODEL / 128, M_TOK / 128, 3);
    gemm_f16cp_kernel<true><<<qkvgrid, 128, GEMM_SMEM>>>(Xp, Wqp, Wkp, Wvp, Qp, Kp, Vp);

    dim3 agrid(B_ * NH, S_ / 128);
    attn_f16_kernel<<<agrid, 256, ATT_SMEM>>>(Qp, Kp, Vp, Ap);

    dim3 ogrid(D_MODEL / 128, M_TOK / 128);
    gemm_f16cp_kernel<false><<<ogrid, 128, GEMM_SMEM>>>(Ap, Wop, nullptr, nullptr, out, nullptr, nullptr);
}

// round 17
// speedup vs baseline: 1.0627x; 1.0627x over previous
#include <cuda_runtime.h>
#include <cuda_fp16.h>
#include <cstdint>
#include <math.h>

#define D_MODEL 1024
#define NH      16
#define DH      64
#define B_      2
#define S_      2048
#define M_TOK   (B_ * S_)

// ---------------- scratch (allocation-free) ----------------
__device__ __half g_X [M_TOK * D_MODEL];
__device__ __half g_Wq[D_MODEL * D_MODEL];
__device__ __half g_Wk[D_MODEL * D_MODEL];
__device__ __half g_Wv[D_MODEL * D_MODEL];
__device__ __half g_Wo[D_MODEL * D_MODEL];
__device__ __half g_Q [M_TOK * D_MODEL];
__device__ __half g_K [M_TOK * D_MODEL];
__device__ __half g_V [M_TOK * D_MODEL];
__device__ __half g_A [M_TOK * D_MODEL];

// ---------------- helpers ----------------
__device__ __forceinline__ uint32_t pack_h2(float a, float b) {
    __half2 h = __floats2half2_rn(a, b);
    return *(uint32_t*)&h;
}
__device__ __forceinline__ void mma_f16(float* c, const uint32_t* a, const uint32_t* b) {
    asm volatile(
        "mma.sync.aligned.m16n8k16.row.col.f32.f16.f16.f32 "
        "{%0,%1,%2,%3}, {%4,%5,%6,%7}, {%8,%9}, {%0,%1,%2,%3};"
        : "+f"(c[0]), "+f"(c[1]), "+f"(c[2]), "+f"(c[3])
        : "r"(a[0]), "r"(a[1]), "r"(a[2]), "r"(a[3]), "r"(b[0]), "r"(b[1]));
}
__device__ __forceinline__ void ldsm_x4(uint32_t* r, uint32_t addr) {
    asm volatile("ldmatrix.sync.aligned.m8n8.x4.shared.b16 {%0,%1,%2,%3}, [%4];"
        : "=r"(r[0]), "=r"(r[1]), "=r"(r[2]), "=r"(r[3]) : "r"(addr));
}
__device__ __forceinline__ void ldsm_x4_t(uint32_t* r, uint32_t addr) {
    asm volatile("ldmatrix.sync.aligned.m8n8.x4.trans.shared.b16 {%0,%1,%2,%3}, [%4];"
        : "=r"(r[0]), "=r"(r[1]), "=r"(r[2]), "=r"(r[3]) : "r"(addr));
}
__device__ __forceinline__ uint32_t smem_u32(const void* p) {
    uint32_t a;
    asm("{ .reg .u64 t; cvta.to.shared.u64 t, %1; cvt.u32.u64 %0, t; }" : "=r"(a) : "l"(p));
    return a;
}
__device__ __forceinline__ void cp_async16(uint32_t dst, const void* src) {
    asm volatile("cp.async.cg.shared.global [%0], [%1], 16;" :: "r"(dst), "l"(src));
}
#define CP_COMMIT() asm volatile("cp.async.commit_group;" ::: "memory")
#define CP_WAIT1()  asm volatile("cp.async.wait_group 1;"  ::: "memory")

// ============================================================================
// Fused fp32 -> fp16 convert. Wq additionally pre-scaled by 0.125 (exact,
// power-of-2: cvt(0.125*w) == 0.125*cvt(w) bit-for-bit) so the QKV epilogue
// needs no scale multiply.
// ============================================================================
#define X4SZ (M_TOK * D_MODEL / 4)
#define W4SZ (D_MODEL * D_MODEL / 4)
#define TOT4 (X4SZ + 4 * W4SZ)

__global__ __launch_bounds__(256) void cvt_all_kernel(
    const float* __restrict__ x,
    const float* __restrict__ wq, const float* __restrict__ wk,
    const float* __restrict__ wv, const float* __restrict__ wo,
    __half* __restrict__ xd,
    __half* __restrict__ wqd, __half* __restrict__ wkd,
    __half* __restrict__ wvd, __half* __restrict__ wod)
{
    for (int i = blockIdx.x * blockDim.x + threadIdx.x; i < TOT4;
         i += gridDim.x * blockDim.x) {
        const float* src; __half* dst; int j;
        float scale = 1.0f;
        if (i < X4SZ) { src = x; dst = xd; j = i; }
        else {
            const int r = i - X4SZ;
            const int s = r >> 18;
            j = r & (W4SZ - 1);
            src = (s == 0) ? wq : (s == 1) ? wk : (s == 2) ? wv : wo;
            dst = (s == 0) ? wqd : (s == 1) ? wkd : (s == 2) ? wvd : wod;
            if (s == 0) scale = 0.125f;    // fold Q prescale into Wq (exact)
        }
        float4 v = ((const float4*)src)[j];
        ((uint2*)dst)[j] = make_uint2(pack_h2(v.x * scale, v.y * scale),
                                      pack_h2(v.z * scale, v.w * scale));
    }
}

// ============================================================================
// All-fp16 NT-GEMM (R14 winner): CTA 128x128, 4 warps (2m x 2n) 64x64 warp
// tiles; k-chunk 64, 3-stage cp.async; 128 threads, 2 CTAs/SM.
// ============================================================================
#define G2STR  36
#define G2SST  (256 * G2STR)             // 9216 words per stage
#define GEMM_SMEM (3 * G2SST * 4)        // 110592 B
#define KITER  (D_MODEL / 64)            // 16

template <bool QKV>
__global__ __launch_bounds__(128, 2) void gemm_f16cp_kernel(
    const __half* __restrict__ A,
    const __half* __restrict__ Wa, const __half* __restrict__ Wb,
    const __half* __restrict__ Wc,
    void* __restrict__ Ca, void* __restrict__ Cb, void* __restrict__ Cc)
{
    extern __shared__ uint32_t sm[];
    const uint32_t sbase = smem_u32(sm);

    const __half* W;
    void* Cv;
    if (QKV) {
        const int z = blockIdx.z;
        W  = (z == 0) ? Wa : (z == 1) ? Wb : Wc;
        Cv = (z == 0) ? Ca : (z == 1) ? Cb : Cc;
    } else {
        W = Wa; Cv = Ca;
    }

    const int tid  = threadIdx.x;
    const int wid  = tid >> 5;
    const int lane = tid & 31;
    const int m0   = blockIdx.y * 128;
    const int n0   = blockIdx.x * 128;
    const int wm   = (wid & 1) * 64;
    const int wn   = (wid >> 1) * 64;

    const int srow = tid >> 3;
    const int sch  = tid & 7;
    auto issue = [&](int i, int p) {
        const int k0 = i * 64;
#pragma unroll
        for (int j = 0; j < 16; j++) {
            const int row = srow + (j & 7) * 16;
            const __half* src = (j < 8)
                ? A + (size_t)(m0 + row) * D_MODEL + k0 + sch * 8
                : W + (size_t)(n0 + row) * D_MODEL + k0 + sch * 8;
            const int lrow = (j < 8) ? row : row + 128;
            cp_async16(sbase + 4 * (p * G2SST + lrow * G2STR + sch * 4), src);
        }
    };

    const int a_off = (lane & 15) * G2STR + (lane >> 4) * 4;
    const int b_off = ((lane & 7) + (lane >> 4) * 8) * G2STR + ((lane >> 3) & 1) * 4;

    float acc[4][8][4];
#pragma unroll
    for (int mt = 0; mt < 4; mt++)
#pragma unroll
        for (int nt = 0; nt < 8; nt++)
#pragma unroll
            for (int e = 0; e < 4; e++) acc[mt][nt][e] = 0.f;

    issue(0, 0); CP_COMMIT();
    issue(1, 1); CP_COMMIT();

    for (int i = 0; i < KITER; i++) {
        CP_WAIT1();
        __syncthreads();

        if (i + 2 < KITER) issue(i + 2, (i + 2) % 3);
        CP_COMMIT();

        const int p = i % 3;
        const uint32_t sA = sbase + 4 * (p * G2SST);
        const uint32_t sB = sbase + 4 * (p * G2SST + 128 * G2STR);

#pragma unroll
        for (int ks = 0; ks < 4; ks++) {
            uint32_t a[4][4], b[4][4];
#pragma unroll
            for (int ma = 0; ma < 4; ma++)
                ldsm_x4(a[ma], sA + 4 * ((wm + ma * 16) * G2STR + ks * 8 + a_off));
#pragma unroll
            for (int nb = 0; nb < 4; nb++)
                ldsm_x4(b[nb], sB + 4 * ((wn + nb * 16) * G2STR + ks * 8 + b_off));
#pragma unroll
            for (int ma = 0; ma < 4; ma++)
#pragma unroll
                for (int nb = 0; nb < 4; nb++) {
                    mma_f16(acc[ma][2 * nb],     a[ma], &b[nb][0]);
                    mma_f16(acc[ma][2 * nb + 1], a[ma], &b[nb][2]);
                }
        }
    }

    const int row  = lane >> 2;
    const int col2 = (lane & 3) * 2;
#pragma unroll
    for (int mt = 0; mt < 4; mt++) {
        const int m = m0 + wm + mt * 16 + row;
#pragma unroll
        for (int nt = 0; nt < 8; nt++) {
            const int n = n0 + wn + nt * 8 + col2;
            if (QKV) {
                uint32_t h01 = pack_h2(acc[mt][nt][0], acc[mt][nt][1]);
                uint32_t h23 = pack_h2(acc[mt][nt][2], acc[mt][nt][3]);
                const int b = m >> 11, s = m & 2047, h = n >> 6, d = n & 63;
                __half* dst = (__half*)Cv + (((size_t)(b * NH + h) * S_) + s) * DH + d;
                *(uint32_t*)dst = h01;
                *(uint32_t*)(dst + (size_t)8 * DH) = h23;
            } else {
                float* dst = (float*)Cv + (size_t)m * D_MODEL + n;
                *(float2*)dst = make_float2(acc[mt][nt][0], acc[mt][nt][1]);
                *(float2*)(dst + 8 * D_MODEL) = make_float2(acc[mt][nt][2], acc[mt][nt][3]);
            }
        }
    }
}

// ============================================================================
// fp16 flash attention (R14 winner): 8 warps x 16-row tiles, Bc=64,
// 3-stage cp.async, globally-descending CTA work order.
// ============================================================================
#define KVS    36
#define VOFFW  (64 * KVS)
#define KVW    (2 * 64 * KVS)
#define PSOFF  (3 * KVW)
#define PSTR   36
#define ATT_SMEM ((PSOFF + 8 * 16 * PSTR) * 4)   // 73728 B

__global__ __launch_bounds__(256, 2) void attn_f16_kernel(
    const __half* __restrict__ Q,
    const __half* __restrict__ K,
    const __half* __restrict__ V,
    __half* __restrict__ O)
{
    extern __shared__ uint32_t sm[];
    const uint32_t sbase = smem_u32(sm);

    const int tid  = threadIdx.x;
    const int wid  = tid >> 5;
    const int lane = tid & 31;
    const int gid  = lane >> 2;
    const int tig  = lane & 3;
    const int bh   = blockIdx.x;
    const int qblk = gridDim.y - 1 - blockIdx.y;
    const int qr0  = qblk * 128 + wid * 16;
    const int ntiles = qblk * 2 + 2;

    const int crow = tid >> 2;
    const int cch  = (tid & 3) * 2;
    const __half* Kg = K + (size_t)bh * S_ * DH;
    const __half* Vg = V + (size_t)bh * S_ * DH;

    auto issue_tile = [&](int t, int p) {
        const size_t row = (size_t)t * 64 + crow;
#pragma unroll
        for (int j = 0; j < 2; j++) {
            const int ch = cch + j;
            cp_async16(sbase + 4 * (p * KVW + crow * KVS + ch * 4),
                       Kg + row * DH + ch * 8);
            cp_async16(sbase + 4 * (p * KVW + VOFFW + crow * KVS + ch * 4),
                       Vg + row * DH + ch * 8);
        }
    };

    const int kb_off = ((lane & 7) + (lane >> 4) * 8) * KVS + ((lane >> 3) & 1) * 4;
    const int v_off  = (lane & 15) * KVS + (lane >> 4) * 4;
    const int p_off  = ((lane & 7) + ((lane >> 3) & 1) * 8) * PSTR + (lane >> 4) * 4;

    const uint32_t* Qw = (const uint32_t*)(Q + ((size_t)bh * S_ + qr0) * DH);
    uint32_t qa[4][4];
#pragma unroll
    for (int ks = 0; ks < 4; ks++) {
        qa[ks][0] = Qw[(size_t)gid * 32 + ks * 8 + tig];
        qa[ks][1] = Qw[(size_t)(gid + 8) * 32 + ks * 8 + tig];
        qa[ks][2] = Qw[(size_t)gid * 32 + ks * 8 + tig + 4];
        qa[ks][3] = Qw[(size_t)(gid + 8) * 32 + ks * 8 + tig + 4];
    }

    float o[8][4];
#pragma unroll
    for (int dt = 0; dt < 8; dt++)
#pragma unroll
        for (int e = 0; e < 4; e++) o[dt][e] = 0.f;
    float mr0 = -1e30f, mr1 = -1e30f;
    float lr0 = 0.f, lr1 = 0.f;

    issue_tile(0, 0); CP_COMMIT();
    issue_tile(1, 1); CP_COMMIT();

    uint32_t* Pw = sm + PSOFF + wid * 16 * PSTR;
    const uint32_t pwbase = sbase + 4 * (PSOFF + wid * 16 * PSTR);

    for (int t = 0; t < ntiles; t++) {
        CP_WAIT1();
        __syncthreads();

        if (t + 2 < ntiles) issue_tile(t + 2, (t + 2) % 3);
        CP_COMMIT();

        const int krow0 = t * 64;
        const int p = t % 3;

        if (krow0 <= qr0 + 15) {
            const uint32_t kbase = sbase + 4 * (p * KVW);
            const uint32_t vbase = sbase + 4 * (p * KVW + VOFFW);

            float sc[8][4];
#pragma unroll
            for (int nt = 0; nt < 8; nt++)
#pragma unroll
                for (int e = 0; e < 4; e++) sc[nt][e] = 0.f;
#pragma unroll
            for (int ks = 0; ks < 4; ks++) {
                uint32_t bk[4][4];
#pragma unroll
                for (int g = 0; g < 4; g++)
                    ldsm_x4(bk[g], kbase + 4 * (g * 16 * KVS + ks * 8 + kb_off));
#pragma unroll
                for (int nt = 0; nt < 8; nt++)
                    mma_f16(sc[nt], qa[ks], &bk[nt >> 1][(nt & 1) * 2]);
            }

            const int row0 = qr0 + gid;
            const int row1 = qr0 + 8 + gid;
            if (krow0 + 63 > qr0) {
#pragma unroll
                for (int nt = 0; nt < 8; nt++) {
                    const int kc = krow0 + nt * 8 + 2 * tig;
                    if (kc > row0)     sc[nt][0] = -1e30f;
                    if (kc + 1 > row0) sc[nt][1] = -1e30f;
                    if (kc > row1)     sc[nt][2] = -1e30f;
                    if (kc + 1 > row1) sc[nt][3] = -1e30f;
                }
            }

            float tmax0 = -1e30f, tmax1 = -1e30f;
#pragma unroll
            for (int nt = 0; nt < 8; nt++) {
                tmax0 = fmaxf(tmax0, fmaxf(sc[nt][0], sc[nt][1]));
                tmax1 = fmaxf(tmax1, fmaxf(sc[nt][2], sc[nt][3]));
            }
            tmax0 = fmaxf(tmax0, __shfl_xor_sync(0xffffffffu, tmax0, 1));
            tmax0 = fmaxf(tmax0, __shfl_xor_sync(0xffffffffu, tmax0, 2));
            tmax1 = fmaxf(tmax1, __shfl_xor_sync(0xffffffffu, tmax1, 1));
            tmax1 = fmaxf(tmax1, __shfl_xor_sync(0xffffffffu, tmax1, 2));

            const float mn0 = fmaxf(mr0, tmax0);
            const float mn1 = fmaxf(mr1, tmax1);
            const float cr0 = __expf(mr0 - mn0);
            const float cr1 = __expf(mr1 - mn1);

            float sum0 = 0.f, sum1 = 0.f;
#pragma unroll
            for (int nt = 0; nt < 8; nt++) {
                float p0 = __expf(sc[nt][0] - mn0);
                float p1 = __expf(sc[nt][1] - mn0);
                float p2 = __expf(sc[nt][2] - mn1);
                float p3 = __expf(sc[nt][3] - mn1);
                sum0 += p0 + p1;
                sum1 += p2 + p3;
                Pw[gid * PSTR + nt * 4 + tig]       = pack_h2(p0, p1);
                Pw[(gid + 8) * PSTR + nt * 4 + tig] = pack_h2(p2, p3);
            }
            sum0 += __shfl_xor_sync(0xffffffffu, sum0, 1);
            sum0 += __shfl_xor_sync(0xffffffffu, sum0, 2);
            sum1 += __shfl_xor_sync(0xffffffffu, sum1, 1);
            sum1 += __shfl_xor_sync(0xffffffffu, sum1, 2);

            lr0 = lr0 * cr0 + sum0;
            lr1 = lr1 * cr1 + sum1;
#pragma unroll
            for (int dt = 0; dt < 8; dt++) {
                o[dt][0] *= cr0; o[dt][1] *= cr0;
                o[dt][2] *= cr1; o[dt][3] *= cr1;
            }
            mr0 = mn0; mr1 = mn1;
            __syncwarp();

#pragma unroll
            for (int kb = 0; kb < 4; kb++) {
                uint32_t pa[4];
                ldsm_x4(pa, pwbase + 4 * (kb * 8 + p_off));
#pragma unroll
                for (int dp = 0; dp < 4; dp++) {
                    uint32_t bv[4];
                    ldsm_x4_t(bv, vbase + 4 * (kb * 16 * KVS + dp * 8 + v_off));
                    mma_f16(o[2 * dp],     pa, &bv[0]);
                    mma_f16(o[2 * dp + 1], pa, &bv[2]);
                }
            }
            __syncwarp();
        }
    }

    const int b  = bh / NH;
    const int h  = bh % NH;
    const float inv0 = 1.f / lr0;
    const float inv1 = 1.f / lr1;
    const int row0 = qr0 + gid;
    const int row1 = qr0 + 8 + gid;
    __half* op0 = O + ((size_t)(b * S_ + row0)) * D_MODEL + h * DH;
    __half* op1 = O + ((size_t)(b * S_ + row1)) * D_MODEL + h * DH;
#pragma unroll
    for (int dt = 0; dt < 8; dt++) {
        const int d = dt * 8 + 2 * tig;
        *(uint32_t*)(op0 + d) = pack_h2(o[dt][0] * inv0, o[dt][1] * inv0);
        *(uint32_t*)(op1 + d) = pack_h2(o[dt][2] * inv1, o[dt][3] * inv1);
    }
}

// ============================================================================
// launch
// ============================================================================
extern "C" void kernel_launch(void* const* d_in, const int* in_sizes, int n_in,
                              void* d_out, int out_size)
{
    const float* x  = (const float*)d_in[0];
    const float* Wq = (const float*)d_in[1];
    const float* Wk = (const float*)d_in[2];
    const float* Wv = (const float*)d_in[3];
    const float* Wo = (const float*)d_in[4];
    float* out = (float*)d_out;

    __half *Xp, *Wqp, *Wkp, *Wvp, *Wop, *Qp, *Kp, *Vp, *Ap;
    cudaGetSymbolAddress((void**)&Xp,  g_X);
    cudaGetSymbolAddress((void**)&Wqp, g_Wq);
    cudaGetSymbolAddress((void**)&Wkp, g_Wk);
    cudaGetSymbolAddress((void**)&Wvp, g_Wv);
    cudaGetSymbolAddress((void**)&Wop, g_Wo);
    cudaGetSymbolAddress((void**)&Qp,  g_Q);
    cudaGetSymbolAddress((void**)&Kp,  g_K);
    cudaGetSymbolAddress((void**)&Vp,  g_V);
    cudaGetSymbolAddress((void**)&Ap,  g_A);

    cudaFuncSetAttribute(gemm_f16cp_kernel<true>,
                         cudaFuncAttributeMaxDynamicSharedMemorySize, GEMM_SMEM);
    cudaFuncSetAttribute(gemm_f16cp_kernel<false>,
                         cudaFuncAttributeMaxDynamicSharedMemorySize, GEMM_SMEM);
    cudaFuncSetAttribute(attn_f16_kernel,
                         cudaFuncAttributeMaxDynamicSharedMemorySize, ATT_SMEM);

    cvt_all_kernel<<<2048, 256>>>(x, Wq, Wk, Wv, Wo, Xp, Wqp, Wkp, Wvp, Wop);

    dim3 qkvgrid(D_MODEL / 128, M_TOK / 128, 3);
    gemm_f16cp_kernel<true><<<qkvgrid, 128, GEMM_SMEM>>>(Xp, Wqp, Wkp, Wvp, Qp, Kp, Vp);

    dim3 agrid(B_ * NH, S_ / 128);
    attn_f16_kernel<<<agrid, 256, ATT_SMEM>>>(Qp, Kp, Vp, Ap);

    dim3 ogrid(D_MODEL / 128, M_TOK / 128);
    gemm_f16cp_kernel<false><<<ogrid, 128, GEMM_SMEM>>>(Ap, Wop, nullptr, nullptr, out, nullptr, nullptr);
}